// round 15
// baseline (speedup 1.0000x reference)
#include <cuda_runtime.h>
#include <cuda_bf16.h>

#define NB 4
#define NC 128
#define HWP (512*512)
#define NL 512
#define TILE 4096
#define NCONS 512                       // consumer threads (warps 0..15)
#define THREADS 544                     // + 1 producer warp
#define PLANEB (TILE * 4)

// dynamic smem offsets (bytes)
#define OFF_RING   0                    // float ring[4][TILE]  = 65536
#define OFF_ENT    65536                // uint ent[TILE]       = 16384
#define OFF_CNT    81920                // int cnt[NL]          = 2048
#define OFF_START  83968                // int start[NL]        = 2048
#define OFF_CURSOR 86016                // int cursor[NL]       = 2048
#define OFF_WSUM   88064                // int wsum[16]         = 64
#define OFF_MBARF  88128                // uint64 full[4]       = 32
#define OFF_MBARE  88160                // uint64 empty[4]      = 32
#define SMEM_BYTES 88192

__device__ int g_counts[NB * NL];
__device__ int g_lab64;   // 1 if labels are int64, 0 if int32

__device__ __forceinline__ void red4(float* p, float a, float b, float c, float d) {
    asm volatile("red.global.add.v4.f32 [%0], {%1,%2,%3,%4};"
                 :: "l"(p), "f"(a), "f"(b), "f"(c), "f"(d) : "memory");
}
__device__ __forceinline__ void mbar_init(unsigned int a, unsigned int cnt) {
    asm volatile("mbarrier.init.shared.b64 [%0], %1;" :: "r"(a), "r"(cnt) : "memory");
}
__device__ __forceinline__ void mbar_expect_tx(unsigned int a, unsigned int bytes) {
    asm volatile("mbarrier.arrive.expect_tx.shared.b64 _, [%0], %1;"
                 :: "r"(a), "r"(bytes) : "memory");
}
__device__ __forceinline__ void mbar_arrive(unsigned int a) {
    asm volatile("mbarrier.arrive.shared.b64 _, [%0];" :: "r"(a) : "memory");
}
__device__ __forceinline__ void mbar_wait(unsigned int a, unsigned int parity) {
    asm volatile(
        "{\n\t"
        ".reg .pred P1;\n\t"
        "WAIT_LOOP_%=:\n\t"
        "mbarrier.try_wait.parity.acquire.cta.shared::cta.b64 P1, [%0], %1, 0x989680;\n\t"
        "@P1 bra.uni WAIT_DONE_%=;\n\t"
        "bra.uni WAIT_LOOP_%=;\n\t"
        "WAIT_DONE_%=:\n\t"
        "}"
        :: "r"(a), "r"(parity) : "memory");
}
__device__ __forceinline__ void bulk_g2s(unsigned int dst, const void* src,
                                         unsigned int bytes, unsigned int mbar) {
    asm volatile(
        "cp.async.bulk.shared::cta.global.mbarrier::complete_tx::bytes [%0], [%1], %2, [%3];"
        :: "r"(dst), "l"(src), "r"(bytes), "r"(mbar) : "memory");
}

__global__ void zero_kernel(float* __restrict__ out, const unsigned int* __restrict__ lab32) {
    int i = blockIdx.x * 256 + threadIdx.x;
    if (i == 0) {
        int is64 = 1;
        for (int k = 0; k < 128; k++) {
            if (lab32[2 * k + 1] != 0u || lab32[2 * k] >= 512u) { is64 = 0; break; }
        }
        g_lab64 = is64;
    }
    if (i < NB * NL * NC) out[i] = 0.0f;
    if (i < NB * NL) g_counts[i] = 0;
}

__global__ __launch_bounds__(THREADS, 2) void accum_kernel(
    const float* __restrict__ x,
    const void* __restrict__ lab_raw,
    float* __restrict__ out)
{
    extern __shared__ char smem[];
    float*        ring   = (float*)(smem + OFF_RING);
    unsigned int* ent    = (unsigned int*)(smem + OFF_ENT);
    int*          cnt    = (int*)(smem + OFF_CNT);
    int*          start_ = (int*)(smem + OFF_START);
    int*          cursor = (int*)(smem + OFF_CURSOR);
    int*          wsum   = (int*)(smem + OFF_WSUM);

    const int b    = blockIdx.y;
    const int p0   = blockIdx.x * TILE;
    const int tid  = threadIdx.x;
    const int lane = tid & 31;
    const int wid  = tid >> 5;
    const bool consumer = (tid < NCONS);

    const unsigned int smem_u32 = (unsigned int)__cvta_generic_to_shared(smem);
    const unsigned int ring_u32 = smem_u32 + OFF_RING;
    const unsigned int mbf_u32  = smem_u32 + OFF_MBARF;
    const unsigned int mbe_u32  = smem_u32 + OFF_MBARE;
    const float* xb = x + (size_t)b * NC * HWP + p0;

    // ---- init barriers; prefetch channels 0..3 into slots 0..3 ----
    if (tid == 0) {
        #pragma unroll
        for (int s = 0; s < 4; s++) {
            mbar_init(mbf_u32 + 8 * s, 1);    // full: completed by TMA tx
            mbar_init(mbe_u32 + 8 * s, 16);   // empty: one arrive per consumer warp
        }
    }
    __syncthreads();
    if (tid == 0) {
        #pragma unroll
        for (int s = 0; s < 4; s++) {
            mbar_expect_tx(mbf_u32 + 8 * s, PLANEB);
            bulk_g2s(ring_u32 + s * PLANEB, xb + (size_t)s * HWP, PLANEB, mbf_u32 + 8 * s);
        }
    }

    // ---- labels into registers (8 per consumer thread) ----
    int lab[8];
    if (consumer) {
        if (g_lab64) {
            const long long* lb = (const long long*)lab_raw + (size_t)b * HWP + p0;
            #pragma unroll
            for (int h = 0; h < 2; h++) {
                int q = tid + h * NCONS;
                #pragma unroll
                for (int j = 0; j < 4; j++)
                    lab[4 * h + j] = ((int)lb[4 * q + j]) & (NL - 1);
            }
        } else {
            const int4* lb = (const int4*)((const int*)lab_raw + (size_t)b * HWP + p0);
            #pragma unroll
            for (int h = 0; h < 2; h++) {
                int4 vv = lb[tid + h * NCONS];
                lab[4 * h + 0] = vv.x & (NL - 1);
                lab[4 * h + 1] = vv.y & (NL - 1);
                lab[4 * h + 2] = vv.z & (NL - 1);
                lab[4 * h + 3] = vv.w & (NL - 1);
            }
        }
    }

    if (tid < NL) cnt[tid] = 0;
    __syncthreads();

    // ---- histogram ----
    if (consumer) {
        #pragma unroll
        for (int k = 0; k < 8; k++) atomicAdd(&cnt[lab[k]], 1);
    }
    __syncthreads();

    // ---- exclusive prefix sum over cnt[512]; barriers unconditional ----
    int v = (tid < NL) ? cnt[tid] : 0;
    int s = v;
    #pragma unroll
    for (int d = 1; d < 32; d <<= 1) {
        int n2 = __shfl_up_sync(0xffffffffu, s, d);
        if (lane >= d) s += n2;
    }
    if (lane == 31 && wid < 16) wsum[wid] = s;
    __syncthreads();
    if (tid < 16) {
        int t = wsum[tid];
        #pragma unroll
        for (int d = 1; d < 16; d <<= 1) {
            int n2 = __shfl_up_sync(0x0000ffffu, t, d);
            if ((int)tid >= d) t += n2;
        }
        wsum[tid] = t;
    }
    __syncthreads();
    if (tid < NL) {
        int excl = s - v + (wid ? wsum[wid - 1] : 0);
        start_[tid]  = excl;
        cursor[tid]  = excl;
        if (v) atomicAdd(&g_counts[b * NL + tid], v);
    }
    __syncthreads();

    // ---- scatter packed entries (label<<12 | pixel), sorted by label ----
    if (consumer) {
        #pragma unroll
        for (int h = 0; h < 2; h++) {
            #pragma unroll
            for (int j = 0; j < 4; j++) {
                int k   = 4 * h + j;
                int pix = 4 * (tid + h * NCONS) + j;
                int l   = lab[k];
                int pos = atomicAdd(&cursor[l], 1);
                ent[pos] = ((unsigned int)l << 12) | (unsigned int)pix;
            }
        }
    }
    __syncthreads();

    // ---- consumer-owned sorted entries ----
    unsigned int er[8];
    int px[8];
    if (consumer) {
        uint4 e0 = *(const uint4*)(ent + 8 * tid);
        uint4 e1 = *(const uint4*)(ent + 8 * tid + 4);
        er[0] = e0.x; er[1] = e0.y; er[2] = e0.z; er[3] = e0.w;
        er[4] = e1.x; er[5] = e1.y; er[6] = e1.z; er[7] = e1.w;
        #pragma unroll
        for (int j = 0; j < 8; j++) px[j] = (int)(er[j] & 4095u);
    }
    __syncthreads();   // ent consumed; pipeline state ready for all warps

    float* ob = out + (size_t)b * NL * NC;

    if (!consumer) {
        // ---- producer warp: refill each slot the moment it drains ----
        if (lane == 0) {
            #pragma unroll 1
            for (int c = 4; c < NC; c++) {
                const int slot = c & 3;
                const unsigned int par_e = (unsigned int)(((c >> 2) - 1) & 1);
                mbar_wait(mbe_u32 + 8 * slot, par_e);   // all 16 warps done with old data
                mbar_expect_tx(mbf_u32 + 8 * slot, PLANEB);
                bulk_g2s(ring_u32 + slot * PLANEB, xb + (size_t)c * HWP,
                         PLANEB, mbf_u32 + 8 * slot);
            }
        }
    } else {
        // ---- consumer warps: fully warp-autonomous channel loop ----
        #pragma unroll 1
        for (int g = 0; g < NC / 4; g++) {
            float4 acc[8];
            #pragma unroll
            for (int j = 0; j < 8; j++) acc[j] = make_float4(0.f, 0.f, 0.f, 0.f);

            const unsigned int par = (unsigned int)(g & 1);
            #pragma unroll
            for (int cc = 0; cc < 4; cc++) {
                mbar_wait(mbf_u32 + 8 * cc, par);
                const float* buf = ring + cc * TILE;
                #pragma unroll
                for (int j = 0; j < 8; j++) {
                    float vv = buf[px[j]];
                    if (cc == 0) acc[j].x += vv;
                    if (cc == 1) acc[j].y += vv;
                    if (cc == 2) acc[j].z += vv;
                    if (cc == 3) acc[j].w += vv;
                }
                __syncwarp();
                if (lane == 0) mbar_arrive(mbe_u32 + 8 * cc);   // this warp done with slot
            }

            // segmented merge -> red4 per run
            float* obg = ob + 4 * g;
            float4 a = acc[0];
            unsigned int pl = er[0] >> 12;
            #pragma unroll
            for (int j = 1; j < 8; j++) {
                unsigned int l = er[j] >> 12;
                if (l != pl) {
                    red4(obg + pl * NC, a.x, a.y, a.z, a.w);
                    a = acc[j]; pl = l;
                } else {
                    a.x += acc[j].x; a.y += acc[j].y; a.z += acc[j].z; a.w += acc[j].w;
                }
            }
            red4(obg + pl * NC, a.x, a.y, a.z, a.w);
        }
    }
}

__global__ void finalize_kernel(float* __restrict__ out) {
    int i = blockIdx.x * 256 + threadIdx.x;
    if (i >= NB * NL * NC) return;
    int bl = i / NC;
    int c = g_counts[bl];
    float cnt = (float)(c > 1 ? c : 1);
    out[i] = out[i] / cnt;
}

extern "C" void kernel_launch(void* const* d_in, const int* in_sizes, int n_in,
                              void* d_out, int out_size) {
    // Resolve input binding by element count — do not trust ordering.
    const float* x;
    const void*  lab;
    if (in_sizes[0] > in_sizes[1]) {
        x   = (const float*)d_in[0];
        lab = d_in[1];
    } else {
        x   = (const float*)d_in[1];
        lab = d_in[0];
    }
    float* out = (float*)d_out;

    cudaFuncSetAttribute(accum_kernel,
                         cudaFuncAttributeMaxDynamicSharedMemorySize, SMEM_BYTES);

    int ztot = NB * NL * NC;  // 262144
    zero_kernel<<<(ztot + 255) / 256, 256>>>(out, (const unsigned int*)lab);

    dim3 grid(HWP / TILE, NB);  // 64 x 4 = 256 CTAs, single wave at 2 CTA/SM
    accum_kernel<<<grid, THREADS, SMEM_BYTES>>>(x, lab, out);

    finalize_kernel<<<(ztot + 255) / 256, 256>>>(out);
}

// round 17
// speedup vs baseline: 1.1343x; 1.1343x over previous
#include <cuda_runtime.h>
#include <cuda_bf16.h>

#define NB 4
#define NC 128
#define HWP (512*512)
#define NL 512
#define TILE 8192
#define THREADS 1024
#define PLANEB (TILE * 4)
#define PXMASK 8191u
#define LSH 13

// dynamic smem offsets (bytes)
#define OFF_RING   0                    // float ring[4][TILE]  = 131072
#define OFF_ENT    131072               // uint ent[TILE]       = 32768
#define OFF_CNT    163840               // int cnt[NL]          = 2048
#define OFF_START  165888               // int start[NL]        = 2048
#define OFF_CURSOR 167936               // int cursor[NL]       = 2048
#define OFF_WSUM   169984               // int wsum[16]         = 64
#define OFF_MBAR   170048               // uint64 full[4]       = 32
#define SMEM_BYTES 170080

__device__ int g_counts[NB * NL];
__device__ int g_lab64;   // 1 if labels are int64, 0 if int32

__device__ __forceinline__ void red4(float* p, float a, float b, float c, float d) {
    asm volatile("red.global.add.v4.f32 [%0], {%1,%2,%3,%4};"
                 :: "l"(p), "f"(a), "f"(b), "f"(c), "f"(d) : "memory");
}
__device__ __forceinline__ void mbar_init(unsigned int a, unsigned int cnt) {
    asm volatile("mbarrier.init.shared.b64 [%0], %1;" :: "r"(a), "r"(cnt) : "memory");
}
__device__ __forceinline__ void mbar_expect_tx(unsigned int a, unsigned int bytes) {
    asm volatile("mbarrier.arrive.expect_tx.shared.b64 _, [%0], %1;"
                 :: "r"(a), "r"(bytes) : "memory");
}
__device__ __forceinline__ void mbar_wait(unsigned int a, unsigned int parity) {
    asm volatile(
        "{\n\t"
        ".reg .pred P1;\n\t"
        "WAIT_LOOP_%=:\n\t"
        "mbarrier.try_wait.parity.acquire.cta.shared::cta.b64 P1, [%0], %1, 0x989680;\n\t"
        "@P1 bra.uni WAIT_DONE_%=;\n\t"
        "bra.uni WAIT_LOOP_%=;\n\t"
        "WAIT_DONE_%=:\n\t"
        "}"
        :: "r"(a), "r"(parity) : "memory");
}
__device__ __forceinline__ void bulk_g2s(unsigned int dst, const void* src,
                                         unsigned int bytes, unsigned int mbar) {
    asm volatile(
        "cp.async.bulk.shared::cta.global.mbarrier::complete_tx::bytes [%0], [%1], %2, [%3];"
        :: "r"(dst), "l"(src), "r"(bytes), "r"(mbar) : "memory");
}

__global__ void zero_kernel(float* __restrict__ out, const unsigned int* __restrict__ lab32) {
    int i = blockIdx.x * 256 + threadIdx.x;
    if (blockIdx.x == 0) {
        // parallel dtype probe: int64-LE labels in [0,512) have all odd words == 0
        __shared__ int bad;
        if (threadIdx.x == 0) bad = 0;
        __syncthreads();
        if (threadIdx.x < 128) {
            unsigned int hi = lab32[2 * threadIdx.x + 1];
            unsigned int lo = lab32[2 * threadIdx.x];
            if (hi != 0u || lo >= 512u) atomicExch(&bad, 1);
        }
        __syncthreads();
        if (threadIdx.x == 0) g_lab64 = bad ? 0 : 1;
    }
    if (i < NB * NL * NC) out[i] = 0.0f;
    if (i < NB * NL) g_counts[i] = 0;
}

__global__ __launch_bounds__(THREADS, 1) void accum_kernel(
    const float* __restrict__ x,
    const void* __restrict__ lab_raw,
    float* __restrict__ out)
{
    extern __shared__ char smem[];
    float*        ring   = (float*)(smem + OFF_RING);
    unsigned int* ent    = (unsigned int*)(smem + OFF_ENT);
    int*          cnt    = (int*)(smem + OFF_CNT);
    int*          start_ = (int*)(smem + OFF_START);
    int*          cursor = (int*)(smem + OFF_CURSOR);
    int*          wsum   = (int*)(smem + OFF_WSUM);

    const int b    = blockIdx.y;
    const int p0   = blockIdx.x * TILE;
    const int tid  = threadIdx.x;
    const int lane = tid & 31;
    const int wid  = tid >> 5;

    const unsigned int smem_u32 = (unsigned int)__cvta_generic_to_shared(smem);
    const unsigned int ring_u32 = smem_u32 + OFF_RING;
    const unsigned int mbar_u32 = smem_u32 + OFF_MBAR;
    const float* xb = x + (size_t)b * NC * HWP + p0;

    // ---- init mbarriers; prefetch channels 0..3 into slots 0..3 ----
    if (tid == 0) {
        #pragma unroll
        for (int s = 0; s < 4; s++) mbar_init(mbar_u32 + 8 * s, 1);
    }
    __syncthreads();
    if (tid == 0) {
        #pragma unroll
        for (int s = 0; s < 4; s++) {
            mbar_expect_tx(mbar_u32 + 8 * s, PLANEB);
            bulk_g2s(ring_u32 + s * PLANEB, xb + (size_t)s * HWP, PLANEB, mbar_u32 + 8 * s);
        }
    }

    // ---- labels into registers (8 per thread; 1024 thr x 8 = 8192) ----
    int lab[8];
    if (g_lab64) {
        const long long* lb = (const long long*)lab_raw + (size_t)b * HWP + p0;
        #pragma unroll
        for (int h = 0; h < 2; h++) {
            int q = tid + h * THREADS;
            #pragma unroll
            for (int j = 0; j < 4; j++)
                lab[4 * h + j] = ((int)lb[4 * q + j]) & (NL - 1);
        }
    } else {
        const int4* lb = (const int4*)((const int*)lab_raw + (size_t)b * HWP + p0);
        #pragma unroll
        for (int h = 0; h < 2; h++) {
            int4 vv = lb[tid + h * THREADS];
            lab[4 * h + 0] = vv.x & (NL - 1);
            lab[4 * h + 1] = vv.y & (NL - 1);
            lab[4 * h + 2] = vv.z & (NL - 1);
            lab[4 * h + 3] = vv.w & (NL - 1);
        }
    }

    if (tid < NL) cnt[tid] = 0;
    __syncthreads();

    // ---- histogram ----
    #pragma unroll
    for (int k = 0; k < 8; k++) atomicAdd(&cnt[lab[k]], 1);
    __syncthreads();

    // ---- exclusive prefix sum over cnt[512]; guarded writes, unconditional barriers ----
    int v = (tid < NL) ? cnt[tid] : 0;
    int s = v;
    #pragma unroll
    for (int d = 1; d < 32; d <<= 1) {
        int n2 = __shfl_up_sync(0xffffffffu, s, d);
        if (lane >= d) s += n2;
    }
    if (lane == 31 && wid < 16) wsum[wid] = s;
    __syncthreads();
    if (tid < 16) {
        int t = wsum[tid];
        #pragma unroll
        for (int d = 1; d < 16; d <<= 1) {
            int n2 = __shfl_up_sync(0x0000ffffu, t, d);
            if ((int)tid >= d) t += n2;
        }
        wsum[tid] = t;
    }
    __syncthreads();
    if (tid < NL) {
        int excl = s - v + (wid ? wsum[wid - 1] : 0);
        start_[tid]  = excl;
        cursor[tid]  = excl;
        if (v) atomicAdd(&g_counts[b * NL + tid], v);
    }
    __syncthreads();

    // ---- scatter packed entries (label<<13 | pixel), sorted by label ----
    #pragma unroll
    for (int h = 0; h < 2; h++) {
        #pragma unroll
        for (int j = 0; j < 4; j++) {
            int k   = 4 * h + j;
            int pix = 4 * (tid + h * THREADS) + j;
            int l   = lab[k];
            int pos = atomicAdd(&cursor[l], 1);
            ent[pos] = ((unsigned int)l << LSH) | (unsigned int)pix;
        }
    }
    __syncthreads();

    // ---- each thread owns 8 consecutive sorted entries ----
    unsigned int er[8];
    {
        uint4 e0 = *(const uint4*)(ent + 8 * tid);
        uint4 e1 = *(const uint4*)(ent + 8 * tid + 4);
        er[0] = e0.x; er[1] = e0.y; er[2] = e0.z; er[3] = e0.w;
        er[4] = e1.x; er[5] = e1.y; er[6] = e1.z; er[7] = e1.w;
    }

    // ---- channel loop: R13-proven block-phased ring, per-entry float4 accumulators ----
    float* ob = out + (size_t)b * NL * NC;

    #pragma unroll 1
    for (int g = 0; g < NC / 4; g++) {
        float4 acc[8];
        #pragma unroll
        for (int j = 0; j < 8; j++) acc[j] = make_float4(0.f, 0.f, 0.f, 0.f);

        const unsigned int par = (unsigned int)(g & 1);
        #pragma unroll
        for (int cc = 0; cc < 4; cc++) {
            const int c = 4 * g + cc;
            mbar_wait(mbar_u32 + 8 * cc, par);
            const float* buf = ring + cc * TILE;
            #pragma unroll
            for (int j = 0; j < 8; j++) {
                float vv = buf[er[j] & PXMASK];
                if (cc == 0) acc[j].x += vv;
                if (cc == 1) acc[j].y += vv;
                if (cc == 2) acc[j].z += vv;
                if (cc == 3) acc[j].w += vv;
            }
            __syncthreads();   // all threads done with slot cc
            if (tid == 0 && c + 4 < NC) {
                mbar_expect_tx(mbar_u32 + 8 * cc, PLANEB);
                bulk_g2s(ring_u32 + cc * PLANEB, xb + (size_t)(c + 4) * HWP,
                         PLANEB, mbar_u32 + 8 * cc);
            }
        }

        // segmented merge -> red4 per run
        float* obg = ob + 4 * g;
        float4 a = acc[0];
        unsigned int pl = er[0] >> LSH;
        #pragma unroll
        for (int j = 1; j < 8; j++) {
            unsigned int l = er[j] >> LSH;
            if (l != pl) {
                red4(obg + pl * NC, a.x, a.y, a.z, a.w);
                a = acc[j]; pl = l;
            } else {
                a.x += acc[j].x; a.y += acc[j].y; a.z += acc[j].z; a.w += acc[j].w;
            }
        }
        red4(obg + pl * NC, a.x, a.y, a.z, a.w);
    }
}

__global__ void finalize_kernel(float* __restrict__ out) {
    int i = blockIdx.x * 256 + threadIdx.x;
    if (i >= NB * NL * NC) return;
    int bl = i / NC;
    int c = g_counts[bl];
    float cnt = (float)(c > 1 ? c : 1);
    out[i] = out[i] / cnt;
}

extern "C" void kernel_launch(void* const* d_in, const int* in_sizes, int n_in,
                              void* d_out, int out_size) {
    // Resolve input binding by element count — do not trust ordering.
    const float* x;
    const void*  lab;
    if (in_sizes[0] > in_sizes[1]) {
        x   = (const float*)d_in[0];
        lab = d_in[1];
    } else {
        x   = (const float*)d_in[1];
        lab = d_in[0];
    }
    float* out = (float*)d_out;

    cudaFuncSetAttribute(accum_kernel,
                         cudaFuncAttributeMaxDynamicSharedMemorySize, SMEM_BYTES);

    int ztot = NB * NL * NC;  // 262144
    zero_kernel<<<(ztot + 255) / 256, 256>>>(out, (const unsigned int*)lab);

    dim3 grid(HWP / TILE, NB);  // 32 x 4 = 128 CTAs, single wave at 1 CTA/SM
    accum_kernel<<<grid, THREADS, SMEM_BYTES>>>(x, lab, out);

    finalize_kernel<<<(ztot + 255) / 256, 256>>>(out);
}